// round 1
// baseline (speedup 1.0000x reference)
#include <cuda_runtime.h>
#include <math.h>

#define Bsz 32
#define Ssz 512
#define Dsz 512
#define Hsz 8
#define Fsz 2048
#define Lsz 4
#define DHsz 64
#define Msz (Bsz*Ssz)   // 16384

// ---------------- scratch (__device__ globals; no runtime allocation) ----------------
__device__ float g_q   [Bsz*Ssz*Dsz];
__device__ float g_k   [Bsz*Ssz*Dsz];
__device__ float g_v   [Bsz*Ssz*Dsz];
__device__ float g_ctx [Bsz*Ssz*Dsz];
__device__ float g_tmp [Bsz*Ssz*Dsz];
__device__ float g_attn[Bsz*Ssz*Dsz];
__device__ float g_x   [Bsz*Ssz*Dsz];
__device__ float g_ffn [Bsz*Ssz*Fsz];
__device__ float g_tf  [Bsz*Ssz];

// ---------------- timestamp convert (runtime int32/int64 detection) ----------------
__global__ void ts_kernel(const void* __restrict__ raw, float* __restrict__ tf, int n) {
    const long long* a64 = (const long long*)raw;
    const int*       a32 = (const int*)raw;
    bool is64 = true;
    #pragma unroll
    for (int i = 0; i < 8; ++i) {
        long long v = a64[i];
        if (v < 0 || v > 20000000LL) is64 = false;
    }
    int i = blockIdx.x * blockDim.x + threadIdx.x;
    if (i < n) tf[i] = is64 ? (float)a64[i] : (float)a32[i];
}

// ---------------- SGEMM: C[M,N] = A[M,K] @ W[K,N] + bias[N] ----------------
// 128x128 block tile, BK=8, 256 threads, 8x8 per-thread register tile.
__global__ void __launch_bounds__(256) gemm_bias_kernel(
    const float* __restrict__ A, const float* __restrict__ W,
    const float* __restrict__ bias, float* __restrict__ C,
    int M, int N, int K)
{
    __shared__ float As[8][128];
    __shared__ float Bs[8][128];
    const int tid = threadIdx.x;
    const int m0 = blockIdx.y * 128;
    const int n0 = blockIdx.x * 128;

    const int a_row  = tid >> 1;          // 0..127
    const int a_k4   = (tid & 1) * 4;     // 0 or 4
    const int b_row  = tid >> 5;          // 0..7
    const int b_col4 = (tid & 31) * 4;    // 0..124

    const int ty = tid >> 4, tx = tid & 15;
    const int cr = ty * 8, cc = tx * 8;

    float acc[8][8];
    #pragma unroll
    for (int i = 0; i < 8; ++i)
        #pragma unroll
        for (int j = 0; j < 8; ++j) acc[i][j] = 0.0f;

    for (int k0 = 0; k0 < K; k0 += 8) {
        float4 av = *(const float4*)(A + (size_t)(m0 + a_row) * K + k0 + a_k4);
        As[a_k4 + 0][a_row] = av.x;
        As[a_k4 + 1][a_row] = av.y;
        As[a_k4 + 2][a_row] = av.z;
        As[a_k4 + 3][a_row] = av.w;
        *(float4*)&Bs[b_row][b_col4] =
            *(const float4*)(W + (size_t)(k0 + b_row) * N + n0 + b_col4);
        __syncthreads();
        #pragma unroll
        for (int kk = 0; kk < 8; ++kk) {
            float a[8], b[8];
            *(float4*)&a[0] = *(float4*)&As[kk][cr];
            *(float4*)&a[4] = *(float4*)&As[kk][cr + 4];
            *(float4*)&b[0] = *(float4*)&Bs[kk][cc];
            *(float4*)&b[4] = *(float4*)&Bs[kk][cc + 4];
            #pragma unroll
            for (int i = 0; i < 8; ++i)
                #pragma unroll
                for (int j = 0; j < 8; ++j)
                    acc[i][j] = fmaf(a[i], b[j], acc[i][j]);
        }
        __syncthreads();
    }
    #pragma unroll
    for (int i = 0; i < 8; ++i) {
        float* crow = C + (size_t)(m0 + cr + i) * N + n0 + cc;
        #pragma unroll
        for (int jj = 0; jj < 8; jj += 4) {
            float4 bv = *(const float4*)(bias + n0 + cc + jj);
            float4 o;
            o.x = acc[i][jj + 0] + bv.x;
            o.y = acc[i][jj + 1] + bv.y;
            o.z = acc[i][jj + 2] + bv.z;
            o.w = acc[i][jj + 3] + bv.w;
            *(float4*)(crow + jj) = o;
        }
    }
}

// ---------------- attention (flash-style, online softmax) ----------------
// grid: (S/64, H, B), 256 threads. QT=KT=64.
// smem layout (floats): QsT[64*65] KsT[64*65] Vs[64*64] Ps[64*65] tq[64] tk[64]
#define ATTN_SMEM_FLOATS (4160*3 + 4096 + 64 + 64)
#define ATTN_SMEM_BYTES  (ATTN_SMEM_FLOATS * 4)

__global__ void __launch_bounds__(256) attn_kernel(
    const float* __restrict__ Q, const float* __restrict__ Kb,
    const float* __restrict__ Vb, const float* __restrict__ tf,
    const float* __restrict__ pbias, float* __restrict__ O)
{
    extern __shared__ float sm[];
    float* QsT = sm;             // [d][row], stride 65
    float* KsT = QsT + 4160;     // [d][row], stride 65
    float* Vs  = KsT + 4160;     // [row][d], stride 64
    float* Ps  = Vs + 4096;      // [row][col], stride 65
    float* tqs = Ps + 4160;
    float* tks = tqs + 64;

    const int q0 = blockIdx.x * 64;
    const int h  = blockIdx.y;
    const int bb = blockIdx.z;
    const int tid = threadIdx.x;
    const int ty = tid >> 4, tx = tid & 15;
    const int ty4 = ty * 4, tx4 = tx * 4;

    // load Q tile (transposed into smem)
    for (int it = tid; it < 1024; it += 256) {
        int r  = it >> 4;
        int c4 = (it & 15) << 2;
        float4 qv = *(const float4*)(Q + (size_t)(bb * Ssz + q0 + r) * Dsz + h * DHsz + c4);
        QsT[(c4 + 0) * 65 + r] = qv.x;
        QsT[(c4 + 1) * 65 + r] = qv.y;
        QsT[(c4 + 2) * 65 + r] = qv.z;
        QsT[(c4 + 3) * 65 + r] = qv.w;
    }
    if (tid < 64) tqs[tid] = tf[bb * Ssz + q0 + tid];

    float m[4], l[4], acc[4][4];
    #pragma unroll
    for (int i = 0; i < 4; ++i) {
        m[i] = -1e30f; l[i] = 0.0f;
        #pragma unroll
        for (int j = 0; j < 4; ++j) acc[i][j] = 0.0f;
    }

    for (int k0 = 0; k0 < Ssz; k0 += 64) {
        __syncthreads();  // protect K/V/P reuse from prior iteration
        for (int it = tid; it < 1024; it += 256) {
            int r  = it >> 4;
            int c4 = (it & 15) << 2;
            const float* kp = Kb + (size_t)(bb * Ssz + k0 + r) * Dsz + h * DHsz + c4;
            const float* vp = Vb + (size_t)(bb * Ssz + k0 + r) * Dsz + h * DHsz + c4;
            float4 kv = *(const float4*)kp;
            KsT[(c4 + 0) * 65 + r] = kv.x;
            KsT[(c4 + 1) * 65 + r] = kv.y;
            KsT[(c4 + 2) * 65 + r] = kv.z;
            KsT[(c4 + 3) * 65 + r] = kv.w;
            *(float4*)&Vs[r * 64 + c4] = *(const float4*)vp;
        }
        if (tid < 64) tks[tid] = tf[bb * Ssz + k0 + tid];
        __syncthreads();

        // S = Q K^T   (4x4 per thread)
        float s[4][4];
        #pragma unroll
        for (int i = 0; i < 4; ++i)
            #pragma unroll
            for (int j = 0; j < 4; ++j) s[i][j] = 0.0f;
        for (int d = 0; d < 64; ++d) {
            float qv[4], kv[4];
            #pragma unroll
            for (int i = 0; i < 4; ++i) qv[i] = QsT[d * 65 + ty4 + i];
            #pragma unroll
            for (int j = 0; j < 4; ++j) kv[j] = KsT[d * 65 + tx4 + j];
            #pragma unroll
            for (int i = 0; i < 4; ++i)
                #pragma unroll
                for (int j = 0; j < 4; ++j)
                    s[i][j] = fmaf(qv[i], kv[j], s[i][j]);
        }

        // scale (timestamp lag) + position bias
        #pragma unroll
        for (int i = 0; i < 4; ++i) {
            float tq = tqs[ty4 + i];
            float4 bias4 = *(const float4*)&pbias[(size_t)(h * Ssz + q0 + ty4 + i) * Ssz + k0 + tx4];
            float bvals[4] = {bias4.x, bias4.y, bias4.z, bias4.w};
            #pragma unroll
            for (int j = 0; j < 4; ++j) {
                float tk = tks[tx4 + j];
                float lag = (tq - tk) * (1.0f / 60000.0f);
                float sc = 9.0f - __fdividef(1.0f, fmaxf(lag, 0.0f) + 1.0f);
                s[i][j] = __fdividef(s[i][j], sc) + bvals[j];
            }
        }

        // online softmax: reduce across the 16-thread tx group (xor masks <= 8)
        #pragma unroll
        for (int i = 0; i < 4; ++i) {
            float mx = fmaxf(fmaxf(s[i][0], s[i][1]), fmaxf(s[i][2], s[i][3]));
            #pragma unroll
            for (int o = 8; o; o >>= 1) mx = fmaxf(mx, __shfl_xor_sync(0xffffffffu, mx, o));
            float mn = fmaxf(m[i], mx);
            float corr = expf(m[i] - mn);
            float rs = 0.0f;
            #pragma unroll
            for (int j = 0; j < 4; ++j) {
                s[i][j] = expf(s[i][j] - mn);
                rs += s[i][j];
            }
            #pragma unroll
            for (int o = 8; o; o >>= 1) rs += __shfl_xor_sync(0xffffffffu, rs, o);
            l[i] = l[i] * corr + rs;
            m[i] = mn;
            #pragma unroll
            for (int j = 0; j < 4; ++j) acc[i][j] *= corr;
            #pragma unroll
            for (int j = 0; j < 4; ++j) Ps[(ty4 + i) * 65 + tx4 + j] = s[i][j];
        }
        __syncthreads();

        // O += P @ V
        for (int c = 0; c < 64; ++c) {
            float pv[4];
            #pragma unroll
            for (int i = 0; i < 4; ++i) pv[i] = Ps[(ty4 + i) * 65 + c];
            float4 vv = *(float4*)&Vs[c * 64 + tx4];
            #pragma unroll
            for (int i = 0; i < 4; ++i) {
                acc[i][0] = fmaf(pv[i], vv.x, acc[i][0]);
                acc[i][1] = fmaf(pv[i], vv.y, acc[i][1]);
                acc[i][2] = fmaf(pv[i], vv.z, acc[i][2]);
                acc[i][3] = fmaf(pv[i], vv.w, acc[i][3]);
            }
        }
    }

    // normalize and write ctx (layout [B,S,H,DH] == [B*S, D])
    #pragma unroll
    for (int i = 0; i < 4; ++i) {
        float inv_l = __fdividef(1.0f, l[i]);
        float4 o;
        o.x = acc[i][0] * inv_l;
        o.y = acc[i][1] * inv_l;
        o.z = acc[i][2] * inv_l;
        o.w = acc[i][3] * inv_l;
        *(float4*)(O + (size_t)(bb * Ssz + q0 + ty4 + i) * Dsz + h * DHsz + tx4) = o;
    }
}

// ---------------- residual + LayerNorm: out = LN(y + res) * g + b ----------------
__global__ void __launch_bounds__(256) ln_res_kernel(
    const float* __restrict__ y, const float* __restrict__ res,
    const float* __restrict__ g, const float* __restrict__ b,
    float* __restrict__ out)
{
    __shared__ float ws[8];
    const int row = blockIdx.x;
    const int tid = threadIdx.x;
    const size_t base = (size_t)row * Dsz;

    float v0 = y[base + tid]       + res[base + tid];
    float v1 = y[base + 256 + tid] + res[base + 256 + tid];

    float s = v0 + v1;
    #pragma unroll
    for (int o = 16; o; o >>= 1) s += __shfl_xor_sync(0xffffffffu, s, o);
    if ((tid & 31) == 0) ws[tid >> 5] = s;
    __syncthreads();
    float tot = 0.0f;
    #pragma unroll
    for (int i = 0; i < 8; ++i) tot += ws[i];
    float mu = tot * (1.0f / Dsz);
    __syncthreads();

    float d0 = v0 - mu, d1 = v1 - mu;
    float s2 = d0 * d0 + d1 * d1;
    #pragma unroll
    for (int o = 16; o; o >>= 1) s2 += __shfl_xor_sync(0xffffffffu, s2, o);
    if ((tid & 31) == 0) ws[tid >> 5] = s2;
    __syncthreads();
    float tot2 = 0.0f;
    #pragma unroll
    for (int i = 0; i < 8; ++i) tot2 += ws[i];
    float var = tot2 * (1.0f / Dsz);
    float rstd = rsqrtf(var + 1e-12f);

    out[base + tid]       = d0 * rstd * g[tid]       + b[tid];
    out[base + 256 + tid] = d1 * rstd * g[256 + tid] + b[256 + tid];
}

// ---------------- GELU (exact, erf) ----------------
__global__ void __launch_bounds__(256) gelu_kernel(float* __restrict__ x, int n4) {
    int i = blockIdx.x * blockDim.x + threadIdx.x;
    for (; i < n4; i += gridDim.x * blockDim.x) {
        float4 v = ((float4*)x)[i];
        v.x = 0.5f * v.x * (1.0f + erff(v.x * 0.70710678118654752f));
        v.y = 0.5f * v.y * (1.0f + erff(v.y * 0.70710678118654752f));
        v.z = 0.5f * v.z * (1.0f + erff(v.z * 0.70710678118654752f));
        v.w = 0.5f * v.w * (1.0f + erff(v.w * 0.70710678118654752f));
        ((float4*)x)[i] = v;
    }
}

// ---------------- launch ----------------
extern "C" void kernel_launch(void* const* d_in, const int* in_sizes, int n_in,
                              void* d_out, int out_size)
{
    const float* hidden = (const float*)d_in[0];
    const float* pbias  = (const float*)d_in[1];
    const void*  ts     = d_in[2];
    const float* Wq = (const float*)d_in[3];
    const float* bq = (const float*)d_in[4];
    const float* Wk = (const float*)d_in[5];
    const float* bk = (const float*)d_in[6];
    const float* Wv = (const float*)d_in[7];
    const float* bv = (const float*)d_in[8];
    const float* Wo = (const float*)d_in[9];
    const float* bo = (const float*)d_in[10];
    const float* ln1g = (const float*)d_in[11];
    const float* ln1b = (const float*)d_in[12];
    const float* Wi = (const float*)d_in[13];
    const float* bi = (const float*)d_in[14];
    const float* Wf = (const float*)d_in[15];
    const float* bfp = (const float*)d_in[16];
    const float* ln2g = (const float*)d_in[17];
    const float* ln2b = (const float*)d_in[18];

    float *q, *k, *v, *ctx, *tmp, *attn, *x, *ffn, *tf;
    cudaGetSymbolAddress((void**)&q,    g_q);
    cudaGetSymbolAddress((void**)&k,    g_k);
    cudaGetSymbolAddress((void**)&v,    g_v);
    cudaGetSymbolAddress((void**)&ctx,  g_ctx);
    cudaGetSymbolAddress((void**)&tmp,  g_tmp);
    cudaGetSymbolAddress((void**)&attn, g_attn);
    cudaGetSymbolAddress((void**)&x,    g_x);
    cudaGetSymbolAddress((void**)&ffn,  g_ffn);
    cudaGetSymbolAddress((void**)&tf,   g_tf);

    cudaFuncSetAttribute(attn_kernel, cudaFuncAttributeMaxDynamicSharedMemorySize,
                         ATTN_SMEM_BYTES);

    ts_kernel<<<64, 256>>>(ts, tf, Bsz * Ssz);

    const dim3 gD(Dsz / 128, Msz / 128);   // N=512
    const dim3 gF(Fsz / 128, Msz / 128);   // N=2048
    const float* xin = hidden;

    for (int l = 0; l < Lsz; ++l) {
        const size_t oDD = (size_t)l * Dsz * Dsz;
        const size_t oDF = (size_t)l * Dsz * Fsz;
        const size_t oFD = (size_t)l * Fsz * Dsz;

        gemm_bias_kernel<<<gD, 256>>>(xin, Wq + oDD, bq + l * Dsz, q, Msz, Dsz, Dsz);
        gemm_bias_kernel<<<gD, 256>>>(xin, Wk + oDD, bk + l * Dsz, k, Msz, Dsz, Dsz);
        gemm_bias_kernel<<<gD, 256>>>(xin, Wv + oDD, bv + l * Dsz, v, Msz, Dsz, Dsz);

        attn_kernel<<<dim3(Ssz / 64, Hsz, Bsz), 256, ATTN_SMEM_BYTES>>>(
            q, k, v, tf, pbias, ctx);

        gemm_bias_kernel<<<gD, 256>>>(ctx, Wo + oDD, bo + l * Dsz, tmp, Msz, Dsz, Dsz);
        ln_res_kernel<<<Msz, 256>>>(tmp, xin, ln1g + l * Dsz, ln1b + l * Dsz, attn);

        gemm_bias_kernel<<<gF, 256>>>(attn, Wi + oDF, bi + l * Fsz, ffn, Msz, Fsz, Dsz);
        gelu_kernel<<<8192, 256>>>(ffn, Bsz * Ssz * Fsz / 4);
        gemm_bias_kernel<<<gD, 256>>>(ffn, Wf + oFD, bfp + l * Dsz, tmp, Msz, Dsz, Fsz);

        float* xout = (l == Lsz - 1) ? (float*)d_out : x;
        ln_res_kernel<<<Msz, 256>>>(tmp, attn, ln2g + l * Dsz, ln2b + l * Dsz, xout);
        xin = x;
    }
}

// round 7
// speedup vs baseline: 1.6507x; 1.6507x over previous
#include <cuda_runtime.h>
#include <cuda_bf16.h>
#include <math.h>

#define Bsz 32
#define Ssz 512
#define Dsz 512
#define Hsz 8
#define Fsz 2048
#define Lsz 4
#define DHsz 64
#define Msz (Bsz*Ssz)   // 16384

// ---------------- scratch (__device__ globals; no runtime allocation) ----------------
__device__ float g_q   [Bsz*Ssz*Dsz];
__device__ float g_k   [Bsz*Ssz*Dsz];
__device__ float g_v   [Bsz*Ssz*Dsz];
__device__ float g_ctx [Bsz*Ssz*Dsz];
__device__ float g_tmp [Bsz*Ssz*Dsz];
__device__ float g_attn[Bsz*Ssz*Dsz];
__device__ float g_x   [Bsz*Ssz*Dsz];
__device__ float g_ffn [Bsz*Ssz*Fsz];
__device__ float g_tf  [Bsz*Ssz];

// ---------------- timestamp convert (runtime int32/int64 detection) ----------------
__global__ void ts_kernel(const void* __restrict__ raw, float* __restrict__ tf, int n) {
    const long long* a64 = (const long long*)raw;
    const int*       a32 = (const int*)raw;
    bool is64 = true;
    #pragma unroll
    for (int i = 0; i < 8; ++i) {
        long long v = a64[i];
        if (v < 0 || v > 20000000LL) is64 = false;
    }
    int i = blockIdx.x * blockDim.x + threadIdx.x;
    if (i < n) tf[i] = is64 ? (float)a64[i] : (float)a32[i];
}

// ================= tensor-core GEMM (bf16x3 split of fp32) =================
// C[M,N] = A[M,K] @ W[K,N] + bias[N]  (optionally exact-GELU fused)
// Block 128x128x32, 256 threads (8 warps, 64x32 warp tiles), double-buffered.
// A smem: [128][40] bf16 (hi & lo planes). B smem: [32][136] bf16 (k-major).

#define BMt 128
#define BNt 128
#define BKt 32
#define APAD 40
#define BPAD 136
#define APLANE (BMt*APAD)        // 5120 elems
#define BPLANE (BKt*BPAD)        // 4352 elems
#define BUFELEMS (2*APLANE + 2*BPLANE)   // 18944 elems
#define GEMM_SMEM_BYTES (2*BUFELEMS*2)   // 75776 bytes

__device__ __forceinline__ unsigned pack2bf(__nv_bfloat16 a, __nv_bfloat16 b) {
    return (unsigned)__bfloat16_as_ushort(a) | ((unsigned)__bfloat16_as_ushort(b) << 16);
}

__device__ __forceinline__ void split4(float4 v, uint2& hi, uint2& lo) {
    __nv_bfloat16 h0 = __float2bfloat16(v.x);
    __nv_bfloat16 h1 = __float2bfloat16(v.y);
    __nv_bfloat16 h2 = __float2bfloat16(v.z);
    __nv_bfloat16 h3 = __float2bfloat16(v.w);
    __nv_bfloat16 l0 = __float2bfloat16(v.x - __bfloat162float(h0));
    __nv_bfloat16 l1 = __float2bfloat16(v.y - __bfloat162float(h1));
    __nv_bfloat16 l2 = __float2bfloat16(v.z - __bfloat162float(h2));
    __nv_bfloat16 l3 = __float2bfloat16(v.w - __bfloat162float(h3));
    hi.x = pack2bf(h0, h1); hi.y = pack2bf(h2, h3);
    lo.x = pack2bf(l0, l1); lo.y = pack2bf(l2, l3);
}

__device__ __forceinline__ void ldm_x4(unsigned r[4], const __nv_bfloat16* p) {
    unsigned addr = (unsigned)__cvta_generic_to_shared(p);
    asm volatile("ldmatrix.sync.aligned.m8n8.x4.shared.b16 {%0,%1,%2,%3}, [%4];"
                 : "=r"(r[0]), "=r"(r[1]), "=r"(r[2]), "=r"(r[3]) : "r"(addr));
}
__device__ __forceinline__ void ldm_x2t(unsigned r[2], const __nv_bfloat16* p) {
    unsigned addr = (unsigned)__cvta_generic_to_shared(p);
    asm volatile("ldmatrix.sync.aligned.m8n8.x2.trans.shared.b16 {%0,%1}, [%2];"
                 : "=r"(r[0]), "=r"(r[1]) : "r"(addr));
}
__device__ __forceinline__ void mma16816(float c[4], const unsigned a[4], const unsigned b[2]) {
    asm volatile("mma.sync.aligned.m16n8k16.row.col.f32.bf16.bf16.f32 "
                 "{%0,%1,%2,%3},{%4,%5,%6,%7},{%8,%9},{%0,%1,%2,%3};"
                 : "+f"(c[0]), "+f"(c[1]), "+f"(c[2]), "+f"(c[3])
                 : "r"(a[0]), "r"(a[1]), "r"(a[2]), "r"(a[3]), "r"(b[0]), "r"(b[1]));
}

__device__ __forceinline__ void stage_store(
    __nv_bfloat16* sAh, __nv_bfloat16* sAl, __nv_bfloat16* sBh, __nv_bfloat16* sBl,
    const float4 ar[4], const float4 br[4],
    int arow, int acg, int bkk, int bc)
{
    __nv_bfloat16* dAh = sAh + arow * APAD + acg;
    __nv_bfloat16* dAl = sAl + arow * APAD + acg;
    #pragma unroll
    for (int i = 0; i < 4; ++i) {
        uint2 hi, lo;
        split4(ar[i], hi, lo);
        *(uint2*)(dAh + i * 4) = hi;
        *(uint2*)(dAl + i * 4) = lo;
    }
    __nv_bfloat16* dBh = sBh + bkk * BPAD + bc;
    __nv_bfloat16* dBl = sBl + bkk * BPAD + bc;
    #pragma unroll
    for (int i = 0; i < 4; ++i) {
        uint2 hi, lo;
        split4(br[i], hi, lo);
        *(uint2*)(dBh + i * 4) = hi;
        *(uint2*)(dBl + i * 4) = lo;
    }
}

__device__ __forceinline__ float gelu1(float x) {
    return 0.5f * x * (1.0f + erff(x * 0.70710678118654752f));
}

__global__ void __launch_bounds__(256) gemm_tc_kernel(
    const float* __restrict__ A, const float* __restrict__ W,
    const float* __restrict__ bias, float* __restrict__ C,
    int M, int N, int K, int fuse_gelu)
{
    extern __shared__ __nv_bfloat16 smraw[];
    const int tid = threadIdx.x;
    const int lane = tid & 31;
    const int warp = tid >> 5;
    const int wm = (warp >> 2) * 64;
    const int wn = (warp & 3) * 32;
    const int m0 = blockIdx.y * BMt;
    const int n0 = blockIdx.x * BNt;

    // staging coords
    const int arow = tid >> 1;
    const int acg  = (tid & 1) * 16;
    const int bkk  = tid >> 3;
    const int bc   = (tid & 7) * 16;

    const float* Agbase = A + (size_t)(m0 + arow) * K + acg;
    const float* Wgbase = W + (size_t)bkk * N + n0 + bc;

    float4 ar[4], br[4];
    #pragma unroll
    for (int i = 0; i < 4; ++i) ar[i] = *(const float4*)(Agbase + i * 4);
    #pragma unroll
    for (int i = 0; i < 4; ++i) br[i] = *(const float4*)(Wgbase + i * 4);

    stage_store(smraw, smraw + APLANE, smraw + 2 * APLANE, smraw + 2 * APLANE + BPLANE,
                ar, br, arow, acg, bkk, bc);
    __syncthreads();

    float acc[4][4][4];
    #pragma unroll
    for (int mt = 0; mt < 4; ++mt)
        #pragma unroll
        for (int nt = 0; nt < 4; ++nt)
            #pragma unroll
            for (int i = 0; i < 4; ++i) acc[mt][nt][i] = 0.0f;

    // precomputed lane offsets for ldmatrix
    const int agrp = lane >> 3;
    const int aRowOff = (lane & 7) + (agrp & 1) * 8;   // within m16 tile
    const int aKOff   = (agrp >> 1) * 8;
    const int l16 = lane & 15;
    const int bKOff = (l16 & 7) + (l16 >> 3) * 8;

    int cur = 0;
    for (int k0 = 0; k0 < K; k0 += BKt) {
        const bool has_next = (k0 + BKt) < K;
        if (has_next) {
            const float* pa = Agbase + k0 + BKt;
            const float* pw = Wgbase + (size_t)(k0 + BKt) * N;
            #pragma unroll
            for (int i = 0; i < 4; ++i) ar[i] = *(const float4*)(pa + i * 4);
            #pragma unroll
            for (int i = 0; i < 4; ++i) br[i] = *(const float4*)(pw + i * 4);
        }

        const __nv_bfloat16* sAh = smraw + cur * BUFELEMS;
        const __nv_bfloat16* sAl = sAh + APLANE;
        const __nv_bfloat16* sBh = sAh + 2 * APLANE;
        const __nv_bfloat16* sBl = sBh + BPLANE;

        #pragma unroll
        for (int kk = 0; kk < BKt; kk += 16) {
            unsigned ahi[4][4], alo[4][4], bhi[4][2], blo[4][2];
            #pragma unroll
            for (int mt = 0; mt < 4; ++mt) {
                const int row = wm + mt * 16 + aRowOff;
                ldm_x4(ahi[mt], sAh + row * APAD + kk + aKOff);
                ldm_x4(alo[mt], sAl + row * APAD + kk + aKOff);
            }
            #pragma unroll
            for (int nt = 0; nt < 4; ++nt) {
                const int col = wn + nt * 8;
                ldm_x2t(bhi[nt], sBh + (kk + bKOff) * BPAD + col);
                ldm_x2t(blo[nt], sBl + (kk + bKOff) * BPAD + col);
            }
            #pragma unroll
            for (int mt = 0; mt < 4; ++mt)
                #pragma unroll
                for (int nt = 0; nt < 4; ++nt) {
                    mma16816(acc[mt][nt], ahi[mt], bhi[nt]);
                    mma16816(acc[mt][nt], alo[mt], bhi[nt]);
                    mma16816(acc[mt][nt], ahi[mt], blo[nt]);
                }
        }

        if (has_next) {
            __nv_bfloat16* d = smraw + (cur ^ 1) * BUFELEMS;
            stage_store(d, d + APLANE, d + 2 * APLANE, d + 2 * APLANE + BPLANE,
                        ar, br, arow, acg, bkk, bc);
        }
        __syncthreads();
        cur ^= 1;
    }

    // epilogue
    const int crow = lane >> 2;
    const int ccol = 2 * (lane & 3);
    #pragma unroll
    for (int mt = 0; mt < 4; ++mt) {
        #pragma unroll
        for (int nt = 0; nt < 4; ++nt) {
            const int col = n0 + wn + nt * 8 + ccol;
            const float b0 = bias[col], b1 = bias[col + 1];
            const int r0 = m0 + wm + mt * 16 + crow;
            float2 o0, o1;
            o0.x = acc[mt][nt][0] + b0; o0.y = acc[mt][nt][1] + b1;
            o1.x = acc[mt][nt][2] + b0; o1.y = acc[mt][nt][3] + b1;
            if (fuse_gelu) {
                o0.x = gelu1(o0.x); o0.y = gelu1(o0.y);
                o1.x = gelu1(o1.x); o1.y = gelu1(o1.y);
            }
            *(float2*)(C + (size_t)r0 * N + col)       = o0;
            *(float2*)(C + (size_t)(r0 + 8) * N + col) = o1;
        }
    }
}

// ---------------- attention (flash-style, online softmax) ----------------
#define ATTN_SMEM_FLOATS (4160*3 + 4096 + 64 + 64)
#define ATTN_SMEM_BYTES  (ATTN_SMEM_FLOATS * 4)

__global__ void __launch_bounds__(256) attn_kernel(
    const float* __restrict__ Q, const float* __restrict__ Kb,
    const float* __restrict__ Vb, const float* __restrict__ tf,
    const float* __restrict__ pbias, float* __restrict__ O)
{
    extern __shared__ float sm[];
    float* QsT = sm;
    float* KsT = QsT + 4160;
    float* Vs  = KsT + 4160;
    float* Ps  = Vs + 4096;
    float* tqs = Ps + 4160;
    float* tks = tqs + 64;

    const int q0 = blockIdx.x * 64;
    const int h  = blockIdx.y;
    const int bb = blockIdx.z;
    const int tid = threadIdx.x;
    const int ty = tid >> 4, tx = tid & 15;
    const int ty4 = ty * 4, tx4 = tx * 4;

    for (int it = tid; it < 1024; it += 256) {
        int r  = it >> 4;
        int c4 = (it & 15) << 2;
        float4 qv = *(const float4*)(Q + (size_t)(bb * Ssz + q0 + r) * Dsz + h * DHsz + c4);
        QsT[(c4 + 0) * 65 + r] = qv.x;
        QsT[(c4 + 1) * 65 + r] = qv.y;
        QsT[(c4 + 2) * 65 + r] = qv.z;
        QsT[(c4 + 3) * 65 + r] = qv.w;
    }
    if (tid < 64) tqs[tid] = tf[bb * Ssz + q0 + tid];

    float m[4], l[4], acc[4][4];
    #pragma unroll
    for (int i = 0; i < 4; ++i) {
        m[i] = -1e30f; l[i] = 0.0f;
        #pragma unroll
        for (int j = 0; j < 4; ++j) acc[i][j] = 0.0f;
    }

    for (int k0 = 0; k0 < Ssz; k0 += 64) {
        __syncthreads();
        for (int it = tid; it < 1024; it += 256) {
            int r  = it >> 4;
            int c4 = (it & 15) << 2;
            const float* kp = Kb + (size_t)(bb * Ssz + k0 + r) * Dsz + h * DHsz + c4;
            const float* vp = Vb + (size_t)(bb * Ssz + k0 + r) * Dsz + h * DHsz + c4;
            float4 kv = *(const float4*)kp;
            KsT[(c4 + 0) * 65 + r] = kv.x;
            KsT[(c4 + 1) * 65 + r] = kv.y;
            KsT[(c4 + 2) * 65 + r] = kv.z;
            KsT[(c4 + 3) * 65 + r] = kv.w;
            *(float4*)&Vs[r * 64 + c4] = *(const float4*)vp;
        }
        if (tid < 64) tks[tid] = tf[bb * Ssz + k0 + tid];
        __syncthreads();

        float s[4][4];
        #pragma unroll
        for (int i = 0; i < 4; ++i)
            #pragma unroll
            for (int j = 0; j < 4; ++j) s[i][j] = 0.0f;
        for (int d = 0; d < 64; ++d) {
            float qv[4], kv[4];
            #pragma unroll
            for (int i = 0; i < 4; ++i) qv[i] = QsT[d * 65 + ty4 + i];
            #pragma unroll
            for (int j = 0; j < 4; ++j) kv[j] = KsT[d * 65 + tx4 + j];
            #pragma unroll
            for (int i = 0; i < 4; ++i)
                #pragma unroll
                for (int j = 0; j < 4; ++j)
                    s[i][j] = fmaf(qv[i], kv[j], s[i][j]);
        }

        #pragma unroll
        for (int i = 0; i < 4; ++i) {
            float tq = tqs[ty4 + i];
            float4 bias4 = *(const float4*)&pbias[(size_t)(h * Ssz + q0 + ty4 + i) * Ssz + k0 + tx4];
            float bvals[4] = {bias4.x, bias4.y, bias4.z, bias4.w};
            #pragma unroll
            for (int j = 0; j < 4; ++j) {
                float tk = tks[tx4 + j];
                float lag = (tq - tk) * (1.0f / 60000.0f);
                float sc = 9.0f - __fdividef(1.0f, fmaxf(lag, 0.0f) + 1.0f);
                s[i][j] = __fdividef(s[i][j], sc) + bvals[j];
            }
        }

        #pragma unroll
        for (int i = 0; i < 4; ++i) {
            float mx = fmaxf(fmaxf(s[i][0], s[i][1]), fmaxf(s[i][2], s[i][3]));
            #pragma unroll
            for (int o = 8; o; o >>= 1) mx = fmaxf(mx, __shfl_xor_sync(0xffffffffu, mx, o));
            float mn = fmaxf(m[i], mx);
            float corr = expf(m[i] - mn);
            float rs = 0.0f;
            #pragma unroll
            for (int j = 0; j < 4; ++j) {
                s[i][j] = expf(s[i][j] - mn);
                rs += s[i][j];
            }
            #pragma unroll
            for (int o = 8; o; o >>= 1) rs += __shfl_xor_sync(0xffffffffu, rs, o);
            l[i] = l[i] * corr + rs;
            m[i] = mn;
            #pragma unroll
            for (int j = 0; j < 4; ++j) acc[i][j] *= corr;
            #pragma unroll
            for (int j = 0; j < 4; ++j) Ps[(ty4 + i) * 65 + tx4 + j] = s[i][j];
        }
        __syncthreads();

        for (int c = 0; c < 64; ++c) {
            float pv[4];
            #pragma unroll
            for (int i = 0; i < 4; ++i) pv[i] = Ps[(ty4 + i) * 65 + c];
            float4 vv = *(float4*)&Vs[c * 64 + tx4];
            #pragma unroll
            for (int i = 0; i < 4; ++i) {
                acc[i][0] = fmaf(pv[i], vv.x, acc[i][0]);
                acc[i][1] = fmaf(pv[i], vv.y, acc[i][1]);
                acc[i][2] = fmaf(pv[i], vv.z, acc[i][2]);
                acc[i][3] = fmaf(pv[i], vv.w, acc[i][3]);
            }
        }
    }

    #pragma unroll
    for (int i = 0; i < 4; ++i) {
        float inv_l = __fdividef(1.0f, l[i]);
        float4 o;
        o.x = acc[i][0] * inv_l;
        o.y = acc[i][1] * inv_l;
        o.z = acc[i][2] * inv_l;
        o.w = acc[i][3] * inv_l;
        *(float4*)(O + (size_t)(bb * Ssz + q0 + ty4 + i) * Dsz + h * DHsz + tx4) = o;
    }
}

// ---------------- residual + LayerNorm ----------------
__global__ void __launch_bounds__(256) ln_res_kernel(
    const float* __restrict__ y, const float* __restrict__ res,
    const float* __restrict__ g, const float* __restrict__ b,
    float* __restrict__ out)
{
    __shared__ float ws[8];
    const int row = blockIdx.x;
    const int tid = threadIdx.x;
    const size_t base = (size_t)row * Dsz;

    float v0 = y[base + tid]       + res[base + tid];
    float v1 = y[base + 256 + tid] + res[base + 256 + tid];

    float s = v0 + v1;
    #pragma unroll
    for (int o = 16; o; o >>= 1) s += __shfl_xor_sync(0xffffffffu, s, o);
    if ((tid & 31) == 0) ws[tid >> 5] = s;
    __syncthreads();
    float tot = 0.0f;
    #pragma unroll
    for (int i = 0; i < 8; ++i) tot += ws[i];
    float mu = tot * (1.0f / Dsz);
    __syncthreads();

    float d0 = v0 - mu, d1 = v1 - mu;
    float s2 = d0 * d0 + d1 * d1;
    #pragma unroll
    for (int o = 16; o; o >>= 1) s2 += __shfl_xor_sync(0xffffffffu, s2, o);
    if ((tid & 31) == 0) ws[tid >> 5] = s2;
    __syncthreads();
    float tot2 = 0.0f;
    #pragma unroll
    for (int i = 0; i < 8; ++i) tot2 += ws[i];
    float var = tot2 * (1.0f / Dsz);
    float rstd = rsqrtf(var + 1e-12f);

    out[base + tid]       = d0 * rstd * g[tid]       + b[tid];
    out[base + 256 + tid] = d1 * rstd * g[256 + tid] + b[256 + tid];
}

// ---------------- launch ----------------
extern "C" void kernel_launch(void* const* d_in, const int* in_sizes, int n_in,
                              void* d_out, int out_size)
{
    const float* hidden = (const float*)d_in[0];
    const float* pbias  = (const float*)d_in[1];
    const void*  ts     = d_in[2];
    const float* Wq = (const float*)d_in[3];
    const float* bq = (const float*)d_in[4];
    const float* Wk = (const float*)d_in[5];
    const float* bk = (const float*)d_in[6];
    const float* Wv = (const float*)d_in[7];
    const float* bv = (const float*)d_in[8];
    const float* Wo = (const float*)d_in[9];
    const float* bo = (const float*)d_in[10];
    const float* ln1g = (const float*)d_in[11];
    const float* ln1b = (const float*)d_in[12];
    const float* Wi = (const float*)d_in[13];
    const float* bi = (const float*)d_in[14];
    const float* Wf = (const float*)d_in[15];
    const float* bfp = (const float*)d_in[16];
    const float* ln2g = (const float*)d_in[17];
    const float* ln2b = (const float*)d_in[18];

    float *q, *k, *v, *ctx, *tmp, *attn, *x, *ffn, *tf;
    cudaGetSymbolAddress((void**)&q,    g_q);
    cudaGetSymbolAddress((void**)&k,    g_k);
    cudaGetSymbolAddress((void**)&v,    g_v);
    cudaGetSymbolAddress((void**)&ctx,  g_ctx);
    cudaGetSymbolAddress((void**)&tmp,  g_tmp);
    cudaGetSymbolAddress((void**)&attn, g_attn);
    cudaGetSymbolAddress((void**)&x,    g_x);
    cudaGetSymbolAddress((void**)&ffn,  g_ffn);
    cudaGetSymbolAddress((void**)&tf,   g_tf);

    cudaFuncSetAttribute(attn_kernel, cudaFuncAttributeMaxDynamicSharedMemorySize,
                         ATTN_SMEM_BYTES);
    cudaFuncSetAttribute(gemm_tc_kernel, cudaFuncAttributeMaxDynamicSharedMemorySize,
                         GEMM_SMEM_BYTES);

    ts_kernel<<<64, 256>>>(ts, tf, Bsz * Ssz);

    const dim3 gD(Dsz / BNt, Msz / BMt);   // (4, 128)
    const dim3 gF(Fsz / BNt, Msz / BMt);   // (16, 128)
    const float* xin = hidden;

    for (int l = 0; l < Lsz; ++l) {
        const size_t oDD = (size_t)l * Dsz * Dsz;
        const size_t oDF = (size_t)l * Dsz * Fsz;
        const size_t oFD = (size_t)l * Fsz * Dsz;

        gemm_tc_kernel<<<gD, 256, GEMM_SMEM_BYTES>>>(xin, Wq + oDD, bq + l * Dsz, q, Msz, Dsz, Dsz, 0);
        gemm_tc_kernel<<<gD, 256, GEMM_SMEM_BYTES>>>(xin, Wk + oDD, bk + l * Dsz, k, Msz, Dsz, Dsz, 0);
        gemm_tc_kernel<<<gD, 256, GEMM_SMEM_BYTES>>>(xin, Wv + oDD, bv + l * Dsz, v, Msz, Dsz, Dsz, 0);

        attn_kernel<<<dim3(Ssz / 64, Hsz, Bsz), 256, ATTN_SMEM_BYTES>>>(
            q, k, v, tf, pbias, ctx);

        gemm_tc_kernel<<<gD, 256, GEMM_SMEM_BYTES>>>(ctx, Wo + oDD, bo + l * Dsz, tmp, Msz, Dsz, Dsz, 0);
        ln_res_kernel<<<Msz, 256>>>(tmp, xin, ln1g + l * Dsz, ln1b + l * Dsz, attn);

        gemm_tc_kernel<<<gF, 256, GEMM_SMEM_BYTES>>>(attn, Wi + oDF, bi + l * Fsz, ffn, Msz, Fsz, Dsz, 1);
        gemm_tc_kernel<<<gD, 256, GEMM_SMEM_BYTES>>>(ffn, Wf + oFD, bfp + l * Dsz, tmp, Msz, Dsz, Fsz, 0);

        float* xout = (l == Lsz - 1) ? (float*)d_out : x;
        ln_res_kernel<<<Msz, 256>>>(tmp, attn, ln2g + l * Dsz, ln2b + l * Dsz, xout);
        xin = x;
    }
}